// round 15
// baseline (speedup 1.0000x reference)
#include <cuda_runtime.h>
#include <math.h>

#define T 4096
#define BS 128
#define PAD 136            // guard rows: all window/prefetch rows provably >= 0
#define PT 4232            // padded rows per plane: T + PAD
#define SUBQ 1058          // PT/4, subplane length (mod-4 swizzle)
#define CAPC 1024          // coef cache entries per list
#define RCAP 512           // run cache entries per list

typedef unsigned long long ull;

// ---------------- device scratch ----------------
__device__ ull    g_cyF[T + 8];               // (df, df) broadcast pairs, run-ordered
__device__ ull    g_czF[T + 8];               // (dfp, dfp)
__device__ ull    g_cyG[T + 8];               // (dg, dg)
__device__ ull    g_czG[T + 8];               // (dgp, dgp)
__device__ int4   g_runF[2052];               // (m0, len, coefBase, 0)
__device__ int4   g_runG[2052];
__device__ int    g_nF, g_nG, g_nrunF, g_nrunG;
__device__ int    g_ready;                    // filters-published flag (monotonic; replays benign)

struct FParams {
    const float* W1[4];
    const float* b1[4];
    const float* W2[4];
    const float* b2[4];
};

// ---------------- math helpers ----------------
__device__ __forceinline__ void make_E(float z0, float z1,
                                       float a1x, float a1y, float a1z,
                                       float a2x, float a2y, float a2z,
                                       float e[9]) {
    float wx = a1x * z0 + a2x * z1;
    float wy = a1y * z0 + a2y * z1;
    float wz = a1z * z0 + a2z * z1;
    float th2 = wx * wx + wy * wy + wz * wz;
    float s, c, c2;
    if (th2 > 1e-6f) {
        float th = sqrtf(th2);
        float sn, cn;
        sincosf(th, &sn, &cn);
        s = sn / th;
        c = cn;
        c2 = (1.f - cn) / th2;
    } else {
        s = 1.f - th2 * (1.f / 6.f);
        c = 1.f - th2 * 0.5f;
        c2 = 0.5f - th2 * (1.f / 24.f);
    }
    e[0] = c + c2 * wx * wx;      e[1] = c2 * wx * wy - s * wz; e[2] = c2 * wx * wz + s * wy;
    e[3] = c2 * wy * wx + s * wz; e[4] = c + c2 * wy * wy;      e[5] = c2 * wy * wz - s * wx;
    e[6] = c2 * wz * wx - s * wy; e[7] = c2 * wz * wy + s * wx; e[8] = c + c2 * wz * wz;
}

__device__ __forceinline__ void mul_right(float X[9], const float e[9]) {
    #pragma unroll
    for (int r = 0; r < 3; r++) {
        float x0 = X[r * 3], x1 = X[r * 3 + 1], x2 = X[r * 3 + 2];
        X[r * 3 + 0] = x0 * e[0] + x1 * e[3] + x2 * e[6];
        X[r * 3 + 1] = x0 * e[1] + x1 * e[4] + x2 * e[7];
        X[r * 3 + 2] = x0 * e[2] + x1 * e[5] + x2 * e[8];
    }
}

__device__ __forceinline__ void mul_left(float X[9], const float L[9]) {
    #pragma unroll
    for (int cc = 0; cc < 3; cc++) {
        float x0 = X[cc], x1 = X[3 + cc], x2 = X[6 + cc];
        X[cc]     = L[0] * x0 + L[1] * x1 + L[2] * x2;
        X[3 + cc] = L[3] * x0 + L[4] * x1 + L[5] * x2;
        X[6 + cc] = L[6] * x0 + L[7] * x1 + L[8] * x2;
    }
}

__device__ void build_runs(const int* tapm, int cnt, int4* runs, int* nrun_out) {
    int nr = 0, i = 0;
    while (i < cnt) {
        int m0 = tapm[i];
        int j = i + 1;
        while (j < cnt && tapm[j] == tapm[j - 1] + 1) j++;
        runs[nr] = make_int4(m0, j - i, i, 0);
        nr++;
        i = j;
    }
    runs[nr] = make_int4(0x7fffffff, 0, 0, 0);  // sentinel
    *nrun_out = nr;
}

// ---------------- FIR helpers ----------------
__device__ __forceinline__ ull f2pair(float a, float b) {
    ull r;
    asm("mov.b64 %0, {%1, %2};" : "=l"(r) : "f"(a), "f"(b));
    return r;
}
__device__ __forceinline__ void fma2(ull& acc, ull a, ull b) {
    asm("fma.rn.f32x2 %0, %1, %2, %0;" : "+l"(acc) : "l"(a), "l"(b));
}
__device__ __forceinline__ void unpck(ull v, float& lo, float& hi) {
    asm("mov.b64 {%0, %1}, %2;" : "=f"(lo), "=f"(hi) : "l"(v));
}

// NP=2 packed walk; all data paths typed u64 (no pack MOVs); prefetch distance 2.
template <bool SH>
__device__ void walk2(const ull* __restrict__ sP0,        // plane A (u64 rows)
                      const ull* __restrict__ ccY,        // (c,c) pairs
                      const ull* __restrict__ ccZ,
                      const int4* __restrict__ runs, int nrun,
                      int k0, int warpKmax,
                      ull accA[2][4], ull accB[2][4]) {
    const ull* sP1 = sP0 + PT;
    for (int ri = 0; ri < nrun; ri++) {
        int4 rn = SH ? runs[ri] : __ldg(&runs[ri]);
        int m0 = rn.x;
        if (m0 > warpKmax) break;
        int L = min(rn.y, warpKmax - m0 + 1);
        int cb = rn.z;
        int rtop = k0 + PAD - m0;

        ull W0[4], W1[4];
        #pragma unroll
        for (int j = 0; j < 4; j++) {
            int rp = rtop + j;
            int off = ((rp & 3) * SUBQ) + (rp >> 2);
            W0[j] = sP0[off];
            W1[j] = sP1[off];
        }
        int offu[4];
        #pragma unroll
        for (int u = 0; u < 4; u++) {
            int rp = rtop - 1 - u;
            offu[u] = ((rp & 3) * SUBQ) + (rp >> 2);
        }
        ull tA[2], tB[2];
        #pragma unroll
        for (int q = 0; q < 2; q++) {
            tA[q] = sP0[offu[q]];
            tB[q] = sP1[offu[q]];
            offu[q] -= 1;
        }

        int i = 0;
        for (; i + 4 <= L; i += 4) {
            #pragma unroll
            for (int u = 0; u < 4; u++) {
                ull cy = SH ? ccY[cb + i + u] : __ldg(&ccY[cb + i + u]);
                ull cz = SH ? ccZ[cb + i + u] : __ldg(&ccZ[cb + i + u]);
                #pragma unroll
                for (int j = 0; j < 4; j++) {
                    int s = (j - u) & 3;
                    fma2(accA[0][j], W0[s], cy);
                    fma2(accB[0][j], W0[s], cz);
                    fma2(accA[1][j], W1[s], cy);
                    fma2(accB[1][j], W1[s], cz);
                }
                int s3 = (3 - u) & 3;
                W0[s3] = tA[u & 1];
                W1[s3] = tB[u & 1];
                int x = (u + 2) & 3;
                tA[u & 1] = sP0[offu[x]];
                tB[u & 1] = sP1[offu[x]];
                offu[x] -= 1;
            }
        }
        #pragma unroll
        for (int u = 0; u < 3; u++) {
            if (i + u < L) {
                ull cy = SH ? ccY[cb + i + u] : __ldg(&ccY[cb + i + u]);
                ull cz = SH ? ccZ[cb + i + u] : __ldg(&ccZ[cb + i + u]);
                #pragma unroll
                for (int j = 0; j < 4; j++) {
                    int s = (j - u) & 3;
                    fma2(accA[0][j], W0[s], cy);
                    fma2(accB[0][j], W0[s], cz);
                    fma2(accA[1][j], W1[s], cy);
                    fma2(accB[1][j], W1[s], cz);
                }
                int s3 = (3 - u) & 3;
                W0[s3] = tA[u & 1];
                W1[s3] = tB[u & 1];
            }
        }
    }
}

// scalar walk for plane 2 (x-component of its float2 rows), pipelined, guard-free
template <bool SH>
__device__ void walk1s(const float* __restrict__ sP2f,    // float view; value at 2*off
                       const float* __restrict__ ccYf,    // df at 2*idx
                       const float* __restrict__ ccZf,    // dfp at 2*idx
                       const int4* __restrict__ runs, int nrun,
                       int k0, int warpKmax,
                       float accA[4], float accB[4]) {
    for (int ri = 0; ri < nrun; ri++) {
        int4 rn = SH ? runs[ri] : __ldg(&runs[ri]);
        int m0 = rn.x;
        if (m0 > warpKmax) break;
        int L = min(rn.y, warpKmax - m0 + 1);
        int cb = rn.z;
        int rtop = k0 + PAD - m0;

        float W[4];
        #pragma unroll
        for (int j = 0; j < 4; j++) {
            int rp = rtop + j;
            W[j] = sP2f[2 * (((rp & 3) * SUBQ) + (rp >> 2))];
        }
        int offu[4];
        #pragma unroll
        for (int u = 0; u < 4; u++) {
            int rp = rtop - 1 - u;
            offu[u] = ((rp & 3) * SUBQ) + (rp >> 2);
        }
        float tW[2];
        #pragma unroll
        for (int q = 0; q < 2; q++) {
            tW[q] = sP2f[2 * offu[q]];
            offu[q] -= 1;
        }

        int i = 0;
        for (; i + 4 <= L; i += 4) {
            #pragma unroll
            for (int u = 0; u < 4; u++) {
                float cy = SH ? ccYf[2 * (cb + i + u)] : __ldg(&ccYf[2 * (cb + i + u)]);
                float cz = SH ? ccZf[2 * (cb + i + u)] : __ldg(&ccZf[2 * (cb + i + u)]);
                #pragma unroll
                for (int j = 0; j < 4; j++) {
                    int s = (j - u) & 3;
                    accA[j] = fmaf(W[s], cy, accA[j]);
                    accB[j] = fmaf(W[s], cz, accB[j]);
                }
                W[(3 - u) & 3] = tW[u & 1];
                int x = (u + 2) & 3;
                tW[u & 1] = sP2f[2 * offu[x]];
                offu[x] -= 1;
            }
        }
        #pragma unroll
        for (int u = 0; u < 3; u++) {
            if (i + u < L) {
                float cy = SH ? ccYf[2 * (cb + i + u)] : __ldg(&ccYf[2 * (cb + i + u)]);
                float cz = SH ? ccZf[2 * (cb + i + u)] : __ldg(&ccZf[2 * (cb + i + u)]);
                #pragma unroll
                for (int j = 0; j < 4; j++) {
                    int s = (j - u) & 3;
                    accA[j] = fmaf(W[s], cy, accA[j]);
                    accB[j] = fmaf(W[s], cz, accB[j]);
                }
                W[(3 - u) & 3] = tW[u & 1];
            }
        }
    }
}

// ---------------- K_all: fused filters + pathdev + FIR ----------------
__global__ void __launch_bounds__(512, 1) k_all(const float* __restrict__ x_data,
                                                const float* __restrict__ A1,
                                                const float* __restrict__ A2,
                                                FParams p,
                                                float* __restrict__ out) {
    extern __shared__ __align__(16) char smem_raw[];
    int tid = threadIdx.x;

    // ================= filters block =================
    if (blockIdx.x == BS) {
        float* sh = (float*)smem_raw;                 // [4][T]
        int* tapmF = (int*)(sh + 4 * T);              // [T]
        int* tapmG = tapmF + T;                       // [T]
        for (int idx = tid; idx < 4 * T; idx += 512) {
            int f = idx >> 12;
            int i = idx & (T - 1);
            float tt = (f < 2) ? (float)(T - 1 - i) : (float)i;  // f, fp reversed
            const float* W1 = p.W1[f];
            const float* b1 = p.b1[f];
            const float* W2 = p.W2[f];
            float acc = p.b2[f][0];
            #pragma unroll
            for (int u = 0; u < 5; u++)
                acc += W2[u] * tanhf(W1[u] * tt + b1[u]);
            sh[f * T + i] = acc;
        }
        __syncthreads();
        int wid = tid >> 5, lane = tid & 31;
        if (wid < 2) {
            int fa = wid * 2, fb = fa + 1;
            ull* cdstY = wid ? g_cyG : g_cyF;
            ull* cdstZ = wid ? g_czG : g_czF;
            int* mdst = wid ? tapmG : tapmF;
            int cnt = 0;
            for (int base = 0; base < T; base += 32) {
                int m = base + lane;
                float da = (m == 0) ? sh[fa * T] : sh[fa * T + m] - sh[fa * T + m - 1];
                float db = (m == 0) ? sh[fb * T] : sh[fb * T + m] - sh[fb * T + m - 1];
                int act = (da != 0.f) || (db != 0.f);
                unsigned mask = __ballot_sync(0xffffffffu, act);
                if (act) {
                    int pos = cnt + __popc(mask & ((1u << lane) - 1u));
                    cdstY[pos] = f2pair(da, da);
                    cdstZ[pos] = f2pair(db, db);
                    mdst[pos] = m;
                }
                cnt += __popc(mask);
            }
            if (lane == 0) {
                if (wid == 0) g_nF = cnt; else g_nG = cnt;
            }
        }
        __syncthreads();
        if (tid == 0)  build_runs(tapmF, g_nF, g_runF, &g_nrunF);
        if (tid == 32) build_runs(tapmG, g_nG, g_runG, &g_nrunG);
        __syncthreads();
        __threadfence();
        if (tid == 0) atomicExch(&g_ready, 1);
        return;
    }

    // ================= pathdev + FIR block =================
    float2* sS  = (float2*)smem_raw;                  // 5*PT float2 = 169280 B
    ull*    sCyF = (ull*)(sS + 5 * PT);               // 8192 B
    ull*    sCzF = sCyF + CAPC;                       // 8192 B
    ull*    sCyG = sCzF + CAPC;                       // 8192 B
    ull*    sCzG = sCyG + CAPC;                       // 8192 B
    int4*   sRF  = (int4*)(sCzG + CAPC);              // 8192 B
    int4*   sRG  = sRF + RCAP;                        // 8192 B
    float*  smf  = (float*)sCyF;                      // scan scratch (18432 B), pre-cache-load only

    int b = blockIdx.x;
    int wid = tid >> 5, lane = tid & 31;

    // ---- pathdev (chunk C = 8 per thread) ----
    {
        const float2* xb = (const float2*)(x_data + (size_t)b * T * 2);
        float a1x = A1[7] - A1[5], a1y = A1[2] - A1[6], a1z = A1[3] - A1[1];
        float a2x = A2[7] - A2[5], a2y = A2[2] - A2[6], a2z = A2[3] - A2[1];

        const int C = 8;
        int t0 = tid * C;

        float P[9] = {1, 0, 0, 0, 1, 0, 0, 0, 1};
        float CS[9] = {0, 0, 0, 0, 0, 0, 0, 0, 0};
        for (int i = 0; i < C; i++) {
            int t = t0 + i;
            if (t > 0) {
                float2 z = xb[t];
                float e[9];
                make_E(z.x, z.y, a1x, a1y, a1z, a2x, a2y, a2z, e);
                mul_right(P, e);
            }
            #pragma unroll
            for (int d = 0; d < 9; d++) CS[d] += P[d];
        }

        float Pw[9];
        #pragma unroll
        for (int d = 0; d < 9; d++) { Pw[d] = P[d]; smf[tid * 9 + d] = P[d]; }
        for (int off = 1; off < 512; off <<= 1) {
            __syncthreads();
            float L[9];
            int has = tid >= off;
            if (has) {
                #pragma unroll
                for (int d = 0; d < 9; d++) L[d] = smf[(tid - off) * 9 + d];
            }
            __syncthreads();
            if (has) {
                mul_left(Pw, L);
                #pragma unroll
                for (int d = 0; d < 9; d++) smf[tid * 9 + d] = Pw[d];
            }
        }
        __syncthreads();
        float PM[9];
        if (tid > 0) {
            #pragma unroll
            for (int d = 0; d < 9; d++) PM[d] = smf[(tid - 1) * 9 + d];
        } else {
            #pragma unroll
            for (int d = 0; d < 9; d++) PM[d] = (d == 0 || d == 4 || d == 8) ? 1.f : 0.f;
        }
        __syncthreads();

        float CSg[9];
        #pragma unroll
        for (int i = 0; i < 3; i++)
            #pragma unroll
            for (int j = 0; j < 3; j++)
                CSg[3 * i + j] = PM[3 * i] * CS[j] + PM[3 * i + 1] * CS[3 + j] + PM[3 * i + 2] * CS[6 + j];

        float Aw[9];
        #pragma unroll
        for (int d = 0; d < 9; d++) { Aw[d] = CSg[d]; smf[tid * 9 + d] = CSg[d]; }
        for (int off = 1; off < 512; off <<= 1) {
            __syncthreads();
            float L[9];
            int has = tid >= off;
            if (has) {
                #pragma unroll
                for (int d = 0; d < 9; d++) L[d] = smf[(tid - off) * 9 + d];
            }
            __syncthreads();
            if (has) {
                #pragma unroll
                for (int d = 0; d < 9; d++) { Aw[d] += L[d]; smf[tid * 9 + d] = Aw[d]; }
            }
        }
        __syncthreads();
        float PS[9];
        if (tid > 0) {
            #pragma unroll
            for (int d = 0; d < 9; d++) PS[d] = smf[(tid - 1) * 9 + d];
        } else {
            #pragma unroll
            for (int d = 0; d < 9; d++) PS[d] = 0.f;
        }
        __syncthreads();   // scan scratch free after this

        float X[9];
        #pragma unroll
        for (int d = 0; d < 9; d++) X[d] = PM[d];
        for (int i = 0; i < C; i++) {
            int t = t0 + i;
            if (t > 0) {
                float2 z = xb[t];
                float e[9];
                make_E(z.x, z.y, a1x, a1y, a1z, a2x, a2y, a2z, e);
                mul_right(X, e);
            }
            #pragma unroll
            for (int d = 0; d < 9; d++) PS[d] += X[d];
            int rp = t + PAD;
            int si = ((rp & 3) * SUBQ) + (rp >> 2);
            // transpose-closed pairing: (0,4) (1,3) (8,-) (2,6) (5,7)
            sS[0 * PT + si] = make_float2(PS[0], PS[4]);
            sS[1 * PT + si] = make_float2(PS[1], PS[3]);
            sS[2 * PT + si] = make_float2(PS[8], 0.f);
            sS[3 * PT + si] = make_float2(PS[2], PS[6]);
            sS[4 * PT + si] = make_float2(PS[5], PS[7]);
        }
        // zero the PAD rows (rp in [0,136) -> entries [0,34) of each subplane)
        for (int i = tid; i < 5 * 4 * 34; i += 512) {
            int pl = i / 136, r = i % 136, s = r / 34, e = r % 34;
            sS[pl * PT + s * SUBQ + e] = make_float2(0.f, 0.f);
        }
    }
    __syncthreads();

    // ---- wait for filters block (all blocks resident: safe spin) ----
    if (tid == 0) {
        while (atomicAdd(&g_ready, 0) == 0) __nanosleep(200);
    }
    __syncthreads();
    __threadfence();

    // ---- load tap/run caches ----
    int nF = g_nF, nG = g_nG, nrF = g_nrunF, nrG = g_nrunG;
    int fits = (nF <= CAPC) && (nG <= CAPC) && (nrF <= RCAP) && (nrG <= RCAP);
    if (fits) {
        for (int i = tid; i < nF; i += 512) { sCyF[i] = g_cyF[i]; sCzF[i] = g_czF[i]; }
        for (int i = tid; i < nG; i += 512) { sCyG[i] = g_cyG[i]; sCzG[i] = g_czG[i]; }
        for (int i = tid; i < nrF; i += 512) sRF[i] = g_runF[i];
        for (int i = tid; i < nrG; i += 512) sRG[i] = g_runG[i];
    }
    __syncthreads();

    const ull* uS = (const ull*)sS;

    // ---- FIR: two k-chunks per warp, paired (w, 31-w) ----
    for (int half = 0; half < 2; half++) {
        int chunk = half ? (31 - wid) : wid;
        int k0 = chunk * 128 + lane * 4;
        int warpKmax = chunk * 128 + 127;
        float* po = out + ((size_t)b * T + (size_t)k0) * 9;

        // ---- pass A: planes 0,1 -> (0,4) noswap | (1,3) swap ----
        {
            ull aF[2][4], aFp[2][4], aG[2][4], aGp[2][4];
            #pragma unroll
            for (int p2 = 0; p2 < 2; p2++)
                #pragma unroll
                for (int j = 0; j < 4; j++) { aF[p2][j] = 0; aFp[p2][j] = 0; aG[p2][j] = 0; aGp[p2][j] = 0; }
            if (fits) {
                walk2<true>(uS + 0 * PT, sCyF, sCzF, sRF, nrF, k0, warpKmax, aF, aFp);
                walk2<true>(uS + 0 * PT, sCyG, sCzG, sRG, nrG, k0, warpKmax, aG, aGp);
            } else {
                walk2<false>(uS + 0 * PT, g_cyF, g_czF, g_runF, nrF, k0, warpKmax, aF, aFp);
                walk2<false>(uS + 0 * PT, g_cyG, g_czG, g_runG, nrG, k0, warpKmax, aG, aGp);
            }
            #pragma unroll
            for (int j = 0; j < 4; j++) {
                float fLo, fHi, pLo, pHi, gLo, gHi, qLo, qHi;
                unpck(aF[0][j], fLo, fHi);  unpck(aFp[0][j], pLo, pHi);
                unpck(aG[0][j], gLo, gHi);  unpck(aGp[0][j], qLo, qHi);
                po[j * 9 + 0] = fLo * gLo + pLo * qLo;
                po[j * 9 + 4] = fHi * gHi + pHi * qHi;
                unpck(aF[1][j], fLo, fHi);  unpck(aFp[1][j], pLo, pHi);
                unpck(aG[1][j], gLo, gHi);  unpck(aGp[1][j], qLo, qHi);
                po[j * 9 + 1] = fHi * gLo + pHi * qLo;
                po[j * 9 + 3] = fLo * gHi + pLo * qHi;
            }
        }

        // ---- pass B: planes 3,4 -> (2,6) swap | (5,7) swap ----
        {
            ull aF[2][4], aFp[2][4], aG[2][4], aGp[2][4];
            #pragma unroll
            for (int p2 = 0; p2 < 2; p2++)
                #pragma unroll
                for (int j = 0; j < 4; j++) { aF[p2][j] = 0; aFp[p2][j] = 0; aG[p2][j] = 0; aGp[p2][j] = 0; }
            if (fits) {
                walk2<true>(uS + 3 * PT, sCyF, sCzF, sRF, nrF, k0, warpKmax, aF, aFp);
                walk2<true>(uS + 3 * PT, sCyG, sCzG, sRG, nrG, k0, warpKmax, aG, aGp);
            } else {
                walk2<false>(uS + 3 * PT, g_cyF, g_czF, g_runF, nrF, k0, warpKmax, aF, aFp);
                walk2<false>(uS + 3 * PT, g_cyG, g_czG, g_runG, nrG, k0, warpKmax, aG, aGp);
            }
            #pragma unroll
            for (int j = 0; j < 4; j++) {
                float fLo, fHi, pLo, pHi, gLo, gHi, qLo, qHi;
                unpck(aF[0][j], fLo, fHi);  unpck(aFp[0][j], pLo, pHi);
                unpck(aG[0][j], gLo, gHi);  unpck(aGp[0][j], qLo, qHi);
                po[j * 9 + 2] = fHi * gLo + pHi * qLo;
                po[j * 9 + 6] = fLo * gHi + pLo * qHi;
                unpck(aF[1][j], fLo, fHi);  unpck(aFp[1][j], pLo, pHi);
                unpck(aG[1][j], gLo, gHi);  unpck(aGp[1][j], qLo, qHi);
                po[j * 9 + 5] = fHi * gLo + pHi * qLo;
                po[j * 9 + 7] = fLo * gHi + pLo * qHi;
            }
        }

        // ---- pass C: plane 2 scalar -> channel 8 ----
        {
            float aF[4] = {0, 0, 0, 0}, aFp[4] = {0, 0, 0, 0};
            float aG[4] = {0, 0, 0, 0}, aGp[4] = {0, 0, 0, 0};
            const float* sP2f = (const float*)(sS + 2 * PT);
            if (fits) {
                walk1s<true>(sP2f, (const float*)sCyF, (const float*)sCzF, sRF, nrF, k0, warpKmax, aF, aFp);
                walk1s<true>(sP2f, (const float*)sCyG, (const float*)sCzG, sRG, nrG, k0, warpKmax, aG, aGp);
            } else {
                walk1s<false>(sP2f, (const float*)g_cyF, (const float*)g_czF, g_runF, nrF, k0, warpKmax, aF, aFp);
                walk1s<false>(sP2f, (const float*)g_cyG, (const float*)g_czG, g_runG, nrG, k0, warpKmax, aG, aGp);
            }
            #pragma unroll
            for (int j = 0; j < 4; j++)
                po[j * 9 + 8] = aF[j] * aG[j] + aFp[j] * aGp[j];
        }
    }
}

// ---------------- launch ----------------
extern "C" void kernel_launch(void* const* d_in, const int* in_sizes, int n_in,
                              void* d_out, int out_size) {
    (void)in_sizes; (void)n_in; (void)out_size;
    const float* x  = (const float*)d_in[0];
    const float* A1 = (const float*)d_in[1];
    const float* A2 = (const float*)d_in[2];
    FParams p;
    for (int f = 0; f < 4; f++) {
        p.W1[f] = (const float*)d_in[3 + 4 * f + 0];
        p.b1[f] = (const float*)d_in[3 + 4 * f + 1];
        p.W2[f] = (const float*)d_in[3 + 4 * f + 2];
        p.b2[f] = (const float*)d_in[3 + 4 * f + 3];
    }

    // smem: planes 169280 + coefs 32768 + runs 16384 = 218432 B
    const int SMEM = 5 * PT * 8 + 4 * CAPC * 8 + 2 * RCAP * 16;
    cudaFuncSetAttribute(k_all, cudaFuncAttributeMaxDynamicSharedMemorySize, SMEM);
    k_all<<<BS + 1, 512, SMEM>>>(x, A1, A2, p, (float*)d_out);
}

// round 16
// speedup vs baseline: 1.0536x; 1.0536x over previous
#include <cuda_runtime.h>
#include <math.h>

#define T 4096
#define BS 128
#define PAD 136            // guard rows: all window/prefetch rows provably >= 0
#define PT 4232            // padded rows per plane: T + PAD
#define SUBQ 1058          // PT/4, subplane length (mod-4 swizzle)
#define CAPC 1024          // coef cache entries per list
#define RCAP 512           // run cache entries per list

typedef unsigned long long ull;

// ---------------- device scratch ----------------
__device__ float4 g_coefF[T + 8];             // (df, df, dfp, dfp), run-ordered
__device__ float4 g_coefG[T + 8];
__device__ int4   g_runF[2052];               // (m0, len, coefBase, 0)
__device__ int4   g_runG[2052];
__device__ int    g_nF, g_nG, g_nrunF, g_nrunG;
__device__ int    g_ready;                    // filters-published flag (monotonic; replays benign)

struct FParams {
    const float* W1[4];
    const float* b1[4];
    const float* W2[4];
    const float* b2[4];
};

// ---------------- math helpers ----------------
__device__ __forceinline__ void make_E(float z0, float z1,
                                       float a1x, float a1y, float a1z,
                                       float a2x, float a2y, float a2z,
                                       float e[9]) {
    float wx = a1x * z0 + a2x * z1;
    float wy = a1y * z0 + a2y * z1;
    float wz = a1z * z0 + a2z * z1;
    float th2 = wx * wx + wy * wy + wz * wz;
    float s, c, c2;
    if (th2 > 1e-6f) {
        float th = sqrtf(th2);
        float sn, cn;
        sincosf(th, &sn, &cn);
        s = sn / th;
        c = cn;
        c2 = (1.f - cn) / th2;
    } else {
        s = 1.f - th2 * (1.f / 6.f);
        c = 1.f - th2 * 0.5f;
        c2 = 0.5f - th2 * (1.f / 24.f);
    }
    e[0] = c + c2 * wx * wx;      e[1] = c2 * wx * wy - s * wz; e[2] = c2 * wx * wz + s * wy;
    e[3] = c2 * wy * wx + s * wz; e[4] = c + c2 * wy * wy;      e[5] = c2 * wy * wz - s * wx;
    e[6] = c2 * wz * wx - s * wy; e[7] = c2 * wz * wy + s * wx; e[8] = c + c2 * wz * wz;
}

__device__ __forceinline__ void mul_right(float X[9], const float e[9]) {
    #pragma unroll
    for (int r = 0; r < 3; r++) {
        float x0 = X[r * 3], x1 = X[r * 3 + 1], x2 = X[r * 3 + 2];
        X[r * 3 + 0] = x0 * e[0] + x1 * e[3] + x2 * e[6];
        X[r * 3 + 1] = x0 * e[1] + x1 * e[4] + x2 * e[7];
        X[r * 3 + 2] = x0 * e[2] + x1 * e[5] + x2 * e[8];
    }
}

__device__ __forceinline__ void mul_left(float X[9], const float L[9]) {
    #pragma unroll
    for (int cc = 0; cc < 3; cc++) {
        float x0 = X[cc], x1 = X[3 + cc], x2 = X[6 + cc];
        X[cc]     = L[0] * x0 + L[1] * x1 + L[2] * x2;
        X[3 + cc] = L[3] * x0 + L[4] * x1 + L[5] * x2;
        X[6 + cc] = L[6] * x0 + L[7] * x1 + L[8] * x2;
    }
}

__device__ void build_runs(const int* tapm, int cnt, int4* runs, int* nrun_out) {
    int nr = 0, i = 0;
    while (i < cnt) {
        int m0 = tapm[i];
        int j = i + 1;
        while (j < cnt && tapm[j] == tapm[j - 1] + 1) j++;
        runs[nr] = make_int4(m0, j - i, i, 0);
        nr++;
        i = j;
    }
    runs[nr] = make_int4(0x7fffffff, 0, 0, 0);  // sentinel
    *nrun_out = nr;
}

// ---------------- FIR helpers ----------------
__device__ __forceinline__ void fma2(ull& acc, ull a, ull b) {
    asm("fma.rn.f32x2 %0, %1, %2, %0;" : "+l"(acc) : "l"(a), "l"(b));
}
__device__ __forceinline__ void unpck(ull v, float& lo, float& hi) {
    asm("mov.b64 {%0, %1}, %2;" : "=f"(lo), "=f"(hi) : "l"(v));
}

// Packed walk over ONE interleaved plane (two channel-pairs per 16B row).
// Window and coefs are ulonglong2: LDS.128 lands directly in FFMA2 operand pairs.
// Prefetch distance 2; guard-free (PAD=136).
template <bool SHC, bool SHR>
__device__ void walk2(const ulonglong2* __restrict__ sP,
                      const ulonglong2* __restrict__ cc0,
                      const int4* __restrict__ runs, int nrun,
                      int k0, int warpKmax,
                      ull accA[2][4], ull accB[2][4]) {
    for (int ri = 0; ri < nrun; ri++) {
        int4 rn = SHR ? runs[ri] : __ldg(&runs[ri]);
        int m0 = rn.x;
        if (m0 > warpKmax) break;
        int L = min(rn.y, warpKmax - m0 + 1);
        const ulonglong2* cc = cc0 + rn.z;
        int rtop = k0 + PAD - m0;

        ulonglong2 W[4];
        #pragma unroll
        for (int j = 0; j < 4; j++) {
            int rp = rtop + j;
            W[j] = sP[((rp & 3) * SUBQ) + (rp >> 2)];
        }
        int offu[4];
        #pragma unroll
        for (int u = 0; u < 4; u++) {
            int rp = rtop - 1 - u;
            offu[u] = ((rp & 3) * SUBQ) + (rp >> 2);
        }
        ulonglong2 tP[2];
        #pragma unroll
        for (int q = 0; q < 2; q++) {
            tP[q] = sP[offu[q]];
            offu[q] -= 1;
        }

        int i = 0;
        for (; i + 4 <= L; i += 4) {
            #pragma unroll
            for (int u = 0; u < 4; u++) {
                ulonglong2 c;
                if (SHC) c = cc[i + u];
                else {
                    const ull* gp = (const ull*)&cc[i + u];
                    c.x = __ldg(gp);
                    c.y = __ldg(gp + 1);
                }
                #pragma unroll
                for (int j = 0; j < 4; j++) {
                    int s = (j - u) & 3;
                    fma2(accA[0][j], W[s].x, c.x);
                    fma2(accB[0][j], W[s].x, c.y);
                    fma2(accA[1][j], W[s].y, c.x);
                    fma2(accB[1][j], W[s].y, c.y);
                }
                int s3 = (3 - u) & 3;
                W[s3] = tP[u & 1];
                int x = (u + 2) & 3;
                tP[u & 1] = sP[offu[x]];
                offu[x] -= 1;
            }
        }
        #pragma unroll
        for (int u = 0; u < 3; u++) {
            if (i + u < L) {
                ulonglong2 c;
                if (SHC) c = cc[i + u];
                else {
                    const ull* gp = (const ull*)&cc[i + u];
                    c.x = __ldg(gp);
                    c.y = __ldg(gp + 1);
                }
                #pragma unroll
                for (int j = 0; j < 4; j++) {
                    int s = (j - u) & 3;
                    fma2(accA[0][j], W[s].x, c.x);
                    fma2(accB[0][j], W[s].x, c.y);
                    fma2(accA[1][j], W[s].y, c.x);
                    fma2(accB[1][j], W[s].y, c.y);
                }
                W[(3 - u) & 3] = tP[u & 1];
            }
        }
    }
}

// scalar walk for channel 8 over a bare float plane, pipelined, guard-free.
// Coef floats read from the float4 coef array: df at 4*idx, dfp at 4*idx+2.
template <bool SHC, bool SHR>
__device__ void walk1s(const float* __restrict__ sPs,
                       const float* __restrict__ ccf,
                       const int4* __restrict__ runs, int nrun,
                       int k0, int warpKmax,
                       float accA[4], float accB[4]) {
    for (int ri = 0; ri < nrun; ri++) {
        int4 rn = SHR ? runs[ri] : __ldg(&runs[ri]);
        int m0 = rn.x;
        if (m0 > warpKmax) break;
        int L = min(rn.y, warpKmax - m0 + 1);
        int cb = rn.z;
        int rtop = k0 + PAD - m0;

        float W[4];
        #pragma unroll
        for (int j = 0; j < 4; j++) {
            int rp = rtop + j;
            W[j] = sPs[((rp & 3) * SUBQ) + (rp >> 2)];
        }
        int offu[4];
        #pragma unroll
        for (int u = 0; u < 4; u++) {
            int rp = rtop - 1 - u;
            offu[u] = ((rp & 3) * SUBQ) + (rp >> 2);
        }
        float tW[2];
        #pragma unroll
        for (int q = 0; q < 2; q++) {
            tW[q] = sPs[offu[q]];
            offu[q] -= 1;
        }

        int i = 0;
        for (; i + 4 <= L; i += 4) {
            #pragma unroll
            for (int u = 0; u < 4; u++) {
                int ci = 4 * (cb + i + u);
                float cy = SHC ? ccf[ci]     : __ldg(&ccf[ci]);
                float cz = SHC ? ccf[ci + 2] : __ldg(&ccf[ci + 2]);
                #pragma unroll
                for (int j = 0; j < 4; j++) {
                    int s = (j - u) & 3;
                    accA[j] = fmaf(W[s], cy, accA[j]);
                    accB[j] = fmaf(W[s], cz, accB[j]);
                }
                W[(3 - u) & 3] = tW[u & 1];
                int x = (u + 2) & 3;
                tW[u & 1] = sPs[offu[x]];
                offu[x] -= 1;
            }
        }
        #pragma unroll
        for (int u = 0; u < 3; u++) {
            if (i + u < L) {
                int ci = 4 * (cb + i + u);
                float cy = SHC ? ccf[ci]     : __ldg(&ccf[ci]);
                float cz = SHC ? ccf[ci + 2] : __ldg(&ccf[ci + 2]);
                #pragma unroll
                for (int j = 0; j < 4; j++) {
                    int s = (j - u) & 3;
                    accA[j] = fmaf(W[s], cy, accA[j]);
                    accB[j] = fmaf(W[s], cz, accB[j]);
                }
                W[(3 - u) & 3] = tW[u & 1];
            }
        }
    }
}

// ---------------- K_all: fused filters + pathdev + FIR ----------------
__global__ void __launch_bounds__(512, 1) k_all(const float* __restrict__ x_data,
                                                const float* __restrict__ A1,
                                                const float* __restrict__ A2,
                                                FParams p,
                                                float* __restrict__ out) {
    extern __shared__ __align__(16) char smem_raw[];
    int tid = threadIdx.x;

    // ================= filters block =================
    if (blockIdx.x == BS) {
        float* sh = (float*)smem_raw;                 // [4][T]
        int* tapmF = (int*)(sh + 4 * T);              // [T]
        int* tapmG = tapmF + T;                       // [T]
        for (int idx = tid; idx < 4 * T; idx += 512) {
            int f = idx >> 12;
            int i = idx & (T - 1);
            float tt = (f < 2) ? (float)(T - 1 - i) : (float)i;  // f, fp reversed
            const float* W1 = p.W1[f];
            const float* b1 = p.b1[f];
            const float* W2 = p.W2[f];
            float acc = p.b2[f][0];
            #pragma unroll
            for (int u = 0; u < 5; u++)
                acc += W2[u] * tanhf(W1[u] * tt + b1[u]);
            sh[f * T + i] = acc;
        }
        __syncthreads();
        int wid = tid >> 5, lane = tid & 31;
        if (wid < 2) {
            int fa = wid * 2, fb = fa + 1;
            float4* cdst = wid ? g_coefG : g_coefF;
            int* mdst = wid ? tapmG : tapmF;
            int cnt = 0;
            for (int base = 0; base < T; base += 32) {
                int m = base + lane;
                float da = (m == 0) ? sh[fa * T] : sh[fa * T + m] - sh[fa * T + m - 1];
                float db = (m == 0) ? sh[fb * T] : sh[fb * T + m] - sh[fb * T + m - 1];
                int act = (da != 0.f) || (db != 0.f);
                unsigned mask = __ballot_sync(0xffffffffu, act);
                if (act) {
                    int pos = cnt + __popc(mask & ((1u << lane) - 1u));
                    cdst[pos] = make_float4(da, da, db, db);
                    mdst[pos] = m;
                }
                cnt += __popc(mask);
            }
            if (lane == 0) {
                if (wid == 0) g_nF = cnt; else g_nG = cnt;
            }
        }
        __syncthreads();
        if (tid == 0)  build_runs(tapmF, g_nF, g_runF, &g_nrunF);
        if (tid == 32) build_runs(tapmG, g_nG, g_runG, &g_nrunG);
        __syncthreads();
        __threadfence();
        if (tid == 0) atomicExch(&g_ready, 1);
        return;
    }

    // ================= pathdev + FIR block =================
    float4* sP01 = (float4*)smem_raw;                 // PT float4 = 67712 B: (S0,S4,S1,S3)
    float4* sP34 = sP01 + PT;                         // 67712 B: (S2,S6,S5,S7)
    float*  sPs  = (float*)(sP34 + PT);               // PT floats = 16928 B: S8
    float4* sCF  = (float4*)(sPs + PT);               // 16384 B
    float4* sCG  = sCF + CAPC;                        // 16384 B
    int4*   sRF  = (int4*)(sCG + CAPC);               // 8192 B
    int4*   sRG  = sRF + RCAP;                        // 8192 B
    float*  smf  = (float*)sCF;                       // scan scratch (18432 B), pre-cache-load only

    int b = blockIdx.x;
    int wid = tid >> 5, lane = tid & 31;

    // ---- pathdev (chunk C = 8 per thread) ----
    {
        const float2* xb = (const float2*)(x_data + (size_t)b * T * 2);
        float a1x = A1[7] - A1[5], a1y = A1[2] - A1[6], a1z = A1[3] - A1[1];
        float a2x = A2[7] - A2[5], a2y = A2[2] - A2[6], a2z = A2[3] - A2[1];

        const int C = 8;
        int t0 = tid * C;

        float P[9] = {1, 0, 0, 0, 1, 0, 0, 0, 1};
        float CS[9] = {0, 0, 0, 0, 0, 0, 0, 0, 0};
        for (int i = 0; i < C; i++) {
            int t = t0 + i;
            if (t > 0) {
                float2 z = xb[t];
                float e[9];
                make_E(z.x, z.y, a1x, a1y, a1z, a2x, a2y, a2z, e);
                mul_right(P, e);
            }
            #pragma unroll
            for (int d = 0; d < 9; d++) CS[d] += P[d];
        }

        float Pw[9];
        #pragma unroll
        for (int d = 0; d < 9; d++) { Pw[d] = P[d]; smf[tid * 9 + d] = P[d]; }
        for (int off = 1; off < 512; off <<= 1) {
            __syncthreads();
            float L[9];
            int has = tid >= off;
            if (has) {
                #pragma unroll
                for (int d = 0; d < 9; d++) L[d] = smf[(tid - off) * 9 + d];
            }
            __syncthreads();
            if (has) {
                mul_left(Pw, L);
                #pragma unroll
                for (int d = 0; d < 9; d++) smf[tid * 9 + d] = Pw[d];
            }
        }
        __syncthreads();
        float PM[9];
        if (tid > 0) {
            #pragma unroll
            for (int d = 0; d < 9; d++) PM[d] = smf[(tid - 1) * 9 + d];
        } else {
            #pragma unroll
            for (int d = 0; d < 9; d++) PM[d] = (d == 0 || d == 4 || d == 8) ? 1.f : 0.f;
        }
        __syncthreads();

        float CSg[9];
        #pragma unroll
        for (int i = 0; i < 3; i++)
            #pragma unroll
            for (int j = 0; j < 3; j++)
                CSg[3 * i + j] = PM[3 * i] * CS[j] + PM[3 * i + 1] * CS[3 + j] + PM[3 * i + 2] * CS[6 + j];

        float Aw[9];
        #pragma unroll
        for (int d = 0; d < 9; d++) { Aw[d] = CSg[d]; smf[tid * 9 + d] = CSg[d]; }
        for (int off = 1; off < 512; off <<= 1) {
            __syncthreads();
            float L[9];
            int has = tid >= off;
            if (has) {
                #pragma unroll
                for (int d = 0; d < 9; d++) L[d] = smf[(tid - off) * 9 + d];
            }
            __syncthreads();
            if (has) {
                #pragma unroll
                for (int d = 0; d < 9; d++) { Aw[d] += L[d]; smf[tid * 9 + d] = Aw[d]; }
            }
        }
        __syncthreads();
        float PS[9];
        if (tid > 0) {
            #pragma unroll
            for (int d = 0; d < 9; d++) PS[d] = smf[(tid - 1) * 9 + d];
        } else {
            #pragma unroll
            for (int d = 0; d < 9; d++) PS[d] = 0.f;
        }
        __syncthreads();   // scan scratch free after this

        float X[9];
        #pragma unroll
        for (int d = 0; d < 9; d++) X[d] = PM[d];
        for (int i = 0; i < C; i++) {
            int t = t0 + i;
            if (t > 0) {
                float2 z = xb[t];
                float e[9];
                make_E(z.x, z.y, a1x, a1y, a1z, a2x, a2y, a2z, e);
                mul_right(X, e);
            }
            #pragma unroll
            for (int d = 0; d < 9; d++) PS[d] += X[d];
            int rp = t + PAD;
            int si = ((rp & 3) * SUBQ) + (rp >> 2);
            sP01[si] = make_float4(PS[0], PS[4], PS[1], PS[3]);
            sP34[si] = make_float4(PS[2], PS[6], PS[5], PS[7]);
            sPs[si]  = PS[8];
        }
        // zero the PAD rows (rp in [0,136) -> entries [0,34) of each subplane)
        for (int i = tid; i < 4 * 34; i += 512) {
            int s = i / 34, e = i % 34;
            int si = s * SUBQ + e;
            sP01[si] = make_float4(0.f, 0.f, 0.f, 0.f);
            sP34[si] = make_float4(0.f, 0.f, 0.f, 0.f);
            sPs[si]  = 0.f;
        }
    }
    __syncthreads();

    // ---- wait for filters block (all blocks resident: safe spin) ----
    if (tid == 0) {
        while (atomicAdd(&g_ready, 0) == 0) __nanosleep(200);
    }
    __syncthreads();
    __threadfence();

    // ---- load tap/run caches ----
    int nF = g_nF, nG = g_nG, nrF = g_nrunF, nrG = g_nrunG;
    int fits = (nF <= CAPC) && (nG <= CAPC) && (nrF <= RCAP) && (nrG <= RCAP);
    if (fits) {
        for (int i = tid; i < nF; i += 512) sCF[i] = g_coefF[i];
        for (int i = tid; i < nG; i += 512) sCG[i] = g_coefG[i];
        for (int i = tid; i < nrF; i += 512) sRF[i] = g_runF[i];
        for (int i = tid; i < nrG; i += 512) sRG[i] = g_runG[i];
    }
    __syncthreads();

    const ulonglong2* uP01 = (const ulonglong2*)sP01;
    const ulonglong2* uP34 = (const ulonglong2*)sP34;
    const ulonglong2* uCF  = (const ulonglong2*)sCF;
    const ulonglong2* uCG  = (const ulonglong2*)sCG;

    // ---- FIR: two k-chunks per warp, paired (w, 31-w) ----
    for (int half = 0; half < 2; half++) {
        int chunk = half ? (31 - wid) : wid;
        int k0 = chunk * 128 + lane * 4;
        int warpKmax = chunk * 128 + 127;
        float* po = out + ((size_t)b * T + (size_t)k0) * 9;

        // ---- pass A: plane01 -> (0,4) noswap | (1,3) swap ----
        {
            ull aF[2][4], aFp[2][4], aG[2][4], aGp[2][4];
            #pragma unroll
            for (int p2 = 0; p2 < 2; p2++)
                #pragma unroll
                for (int j = 0; j < 4; j++) { aF[p2][j] = 0; aFp[p2][j] = 0; aG[p2][j] = 0; aGp[p2][j] = 0; }
            if (fits) {
                walk2<true, true>(uP01, uCF, sRF, nrF, k0, warpKmax, aF, aFp);
                walk2<true, true>(uP01, uCG, sRG, nrG, k0, warpKmax, aG, aGp);
            } else {
                walk2<false, false>(uP01, (const ulonglong2*)g_coefF, g_runF, nrF, k0, warpKmax, aF, aFp);
                walk2<false, false>(uP01, (const ulonglong2*)g_coefG, g_runG, nrG, k0, warpKmax, aG, aGp);
            }
            #pragma unroll
            for (int j = 0; j < 4; j++) {
                float fLo, fHi, pLo, pHi, gLo, gHi, qLo, qHi;
                unpck(aF[0][j], fLo, fHi);  unpck(aFp[0][j], pLo, pHi);
                unpck(aG[0][j], gLo, gHi);  unpck(aGp[0][j], qLo, qHi);
                po[j * 9 + 0] = fLo * gLo + pLo * qLo;
                po[j * 9 + 4] = fHi * gHi + pHi * qHi;
                unpck(aF[1][j], fLo, fHi);  unpck(aFp[1][j], pLo, pHi);
                unpck(aG[1][j], gLo, gHi);  unpck(aGp[1][j], qLo, qHi);
                po[j * 9 + 1] = fHi * gLo + pHi * qLo;
                po[j * 9 + 3] = fLo * gHi + pLo * qHi;
            }
        }

        // ---- pass B: plane34 -> (2,6) swap | (5,7) swap ----
        {
            ull aF[2][4], aFp[2][4], aG[2][4], aGp[2][4];
            #pragma unroll
            for (int p2 = 0; p2 < 2; p2++)
                #pragma unroll
                for (int j = 0; j < 4; j++) { aF[p2][j] = 0; aFp[p2][j] = 0; aG[p2][j] = 0; aGp[p2][j] = 0; }
            if (fits) {
                walk2<true, true>(uP34, uCF, sRF, nrF, k0, warpKmax, aF, aFp);
                walk2<true, true>(uP34, uCG, sRG, nrG, k0, warpKmax, aG, aGp);
            } else {
                walk2<false, false>(uP34, (const ulonglong2*)g_coefF, g_runF, nrF, k0, warpKmax, aF, aFp);
                walk2<false, false>(uP34, (const ulonglong2*)g_coefG, g_runG, nrG, k0, warpKmax, aG, aGp);
            }
            #pragma unroll
            for (int j = 0; j < 4; j++) {
                float fLo, fHi, pLo, pHi, gLo, gHi, qLo, qHi;
                unpck(aF[0][j], fLo, fHi);  unpck(aFp[0][j], pLo, pHi);
                unpck(aG[0][j], gLo, gHi);  unpck(aGp[0][j], qLo, qHi);
                po[j * 9 + 2] = fHi * gLo + pHi * qLo;
                po[j * 9 + 6] = fLo * gHi + pLo * qHi;
                unpck(aF[1][j], fLo, fHi);  unpck(aFp[1][j], pLo, pHi);
                unpck(aG[1][j], gLo, gHi);  unpck(aGp[1][j], qLo, qHi);
                po[j * 9 + 5] = fHi * gLo + pHi * qLo;
                po[j * 9 + 7] = fLo * gHi + pLo * qHi;
            }
        }

        // ---- pass C: scalar plane -> channel 8 ----
        {
            float aF[4] = {0, 0, 0, 0}, aFp[4] = {0, 0, 0, 0};
            float aG[4] = {0, 0, 0, 0}, aGp[4] = {0, 0, 0, 0};
            if (fits) {
                walk1s<true, true>(sPs, (const float*)sCF, sRF, nrF, k0, warpKmax, aF, aFp);
                walk1s<true, true>(sPs, (const float*)sCG, sRG, nrG, k0, warpKmax, aG, aGp);
            } else {
                walk1s<false, false>(sPs, (const float*)g_coefF, g_runF, nrF, k0, warpKmax, aF, aFp);
                walk1s<false, false>(sPs, (const float*)g_coefG, g_runG, nrG, k0, warpKmax, aG, aGp);
            }
            #pragma unroll
            for (int j = 0; j < 4; j++)
                po[j * 9 + 8] = aF[j] * aG[j] + aFp[j] * aGp[j];
        }
    }
}

// ---------------- launch ----------------
extern "C" void kernel_launch(void* const* d_in, const int* in_sizes, int n_in,
                              void* d_out, int out_size) {
    (void)in_sizes; (void)n_in; (void)out_size;
    const float* x  = (const float*)d_in[0];
    const float* A1 = (const float*)d_in[1];
    const float* A2 = (const float*)d_in[2];
    FParams p;
    for (int f = 0; f < 4; f++) {
        p.W1[f] = (const float*)d_in[3 + 4 * f + 0];
        p.b1[f] = (const float*)d_in[3 + 4 * f + 1];
        p.W2[f] = (const float*)d_in[3 + 4 * f + 2];
        p.b2[f] = (const float*)d_in[3 + 4 * f + 3];
    }

    // smem: planes 2*67712 + 16928 + coefs 32768 + runs 16384 = 201504 B
    const int SMEM = 2 * PT * 16 + PT * 4 + 2 * CAPC * 16 + 2 * RCAP * 16;
    cudaFuncSetAttribute(k_all, cudaFuncAttributeMaxDynamicSharedMemorySize, SMEM);
    k_all<<<BS + 1, 512, SMEM>>>(x, A1, A2, p, (float*)d_out);
}